// round 15
// baseline (speedup 1.0000x reference)
#include <cuda_runtime.h>
#include <cuda_bf16.h>
#include <cstdint>
#include <math.h>

// Problem dims (fixed by the reference)
constexpr int T_STEPS = 512;
constexpr int NB      = 64;     // batch
constexpr int ID      = 1024;   // input dim
constexpr int HD      = 2048;   // hidden dim
constexpr int TBM     = T_STEPS * NB;   // 32768 rows
constexpr int NCTA    = 128;    // persistent-kernel grid (<= 148 SMs -> co-resident)

// ---------------- scratch (device globals; no cudaMalloc allowed) ------------
__device__ float g_XG  [(size_t)TBM * 3 * HD];            // X@Wx{z,r,h}+b  (TB, 6144)
__device__ float g_Hall[(size_t)(T_STEPS + 1) * NB * HD]; // H_0..H_T (fp32 history)
__device__ float g_Z   [NB * HD];                          // Z gate (fp32)

__device__ __nv_bfloat16 g_Wzr_hi[(size_t)HD * 2 * HD];    // [W_hz|W_hr] bf16 hi
__device__ __nv_bfloat16 g_Wzr_lo[(size_t)HD * 2 * HD];    //              bf16 lo
__device__ __nv_bfloat16 g_Whh_hi[(size_t)HD * HD];
__device__ __nv_bfloat16 g_Whh_lo[(size_t)HD * HD];
__device__ __nv_bfloat16 g_H_hi [NB * HD];                 // current H (bf16 split)
__device__ __nv_bfloat16 g_H_lo [NB * HD];
__device__ __nv_bfloat16 g_RH_hi[NB * HD];                 // R*H (bf16 split)
__device__ __nv_bfloat16 g_RH_lo[NB * HD];

__device__ unsigned g_bar_cnt = 0;
__device__ unsigned g_bar_gen = 0;

// ---------------- mma helpers ------------------------------------------------
__device__ __forceinline__ uint32_t smem_u32(const void* p) {
    return (uint32_t)__cvta_generic_to_shared(p);
}
__device__ __forceinline__ void ldm_x4(uint32_t* r, uint32_t a) {
    asm volatile("ldmatrix.sync.aligned.m8n8.x4.shared.b16 {%0,%1,%2,%3}, [%4];"
                 : "=r"(r[0]), "=r"(r[1]), "=r"(r[2]), "=r"(r[3]) : "r"(a));
}
__device__ __forceinline__ void ldm_x2t(uint32_t* r, uint32_t a) {
    asm volatile("ldmatrix.sync.aligned.m8n8.x2.trans.shared.b16 {%0,%1}, [%2];"
                 : "=r"(r[0]), "=r"(r[1]) : "r"(a));
}
__device__ __forceinline__ void mma_bf16(float* c, const uint32_t* a, const uint32_t* b) {
    asm volatile("mma.sync.aligned.m16n8k16.row.col.f32.bf16.bf16.f32 "
                 "{%0,%1,%2,%3}, {%4,%5,%6,%7}, {%8,%9}, {%0,%1,%2,%3};"
                 : "+f"(c[0]), "+f"(c[1]), "+f"(c[2]), "+f"(c[3])
                 : "r"(a[0]), "r"(a[1]), "r"(a[2]), "r"(a[3]),
                   "r"(b[0]), "r"(b[1]));
}
__device__ __forceinline__ float sigmoidf_(float x) { return 1.f / (1.f + __expf(-x)); }

// ================= big GEMM (phases A & C) — proven template ==================
// C = A(MxK) @ B(KxN) + bias, fp32 in/out, bf16 split-3 tensor-core compute.
template <int BM, int BN, int WM, int WN>
__global__ void __launch_bounds__(32 * (BM / WM) * (BN / WN))
gemm_split3(const float* __restrict__ A, int lda,
            const float* __restrict__ B, int ldb,
            float* __restrict__ C, int ldc,
            int M, int N, int K_total,
            const float* __restrict__ bias)
{
    constexpr int BK      = 16;
    constexpr int WARPS_M = BM / WM;
    constexpr int WARPS_N = BN / WN;
    constexpr int THREADS = 32 * WARPS_M * WARPS_N;
    constexpr int MI = WM / 16, NI = WN / 8;
    constexpr int LDA_S = BK + 8;
    constexpr int LDB_S = BN + 8;

    __shared__ __align__(16) __nv_bfloat16 sAh[BM][LDA_S];
    __shared__ __align__(16) __nv_bfloat16 sAl[BM][LDA_S];
    __shared__ __align__(16) __nv_bfloat16 sBh[BK][LDB_S];
    __shared__ __align__(16) __nv_bfloat16 sBl[BK][LDB_S];

    const int tid  = threadIdx.x;
    const int lane = tid & 31;
    const int warp = tid >> 5;
    const int wm   = (warp % WARPS_M) * WM;
    const int wn   = (warp / WARPS_M) * WN;
    const int bm   = blockIdx.y * BM;
    const int bn   = blockIdx.x * BN;

    float acc[MI][NI][4];
    #pragma unroll
    for (int mi = 0; mi < MI; mi++)
        #pragma unroll
        for (int ni = 0; ni < NI; ni++)
            #pragma unroll
            for (int j = 0; j < 4; j++) acc[mi][ni][j] = 0.f;

    constexpr int A_V = (BM * BK) / (THREADS * 4);
    constexpr int B_V = (BK * BN) / (THREADS * 4);

    for (int kk = 0; kk < K_total; kk += BK) {
        #pragma unroll
        for (int v = 0; v < A_V; v++) {
            int linear = (tid + v * THREADS) * 4;
            int r = linear / BK, c = linear % BK;
            float4 f = make_float4(0.f, 0.f, 0.f, 0.f);
            int gr = bm + r;
            if (gr < M)
                f = *reinterpret_cast<const float4*>(A + (size_t)gr * lda + (kk + c));
            float xv[4] = {f.x, f.y, f.z, f.w};
            #pragma unroll
            for (int j = 0; j < 4; j++) {
                __nv_bfloat16 h = __float2bfloat16(xv[j]);
                sAh[r][c + j] = h;
                sAl[r][c + j] = __float2bfloat16(xv[j] - __bfloat162float(h));
            }
        }
        #pragma unroll
        for (int v = 0; v < B_V; v++) {
            int linear = (tid + v * THREADS) * 4;
            int r = linear / BN, c = linear % BN;
            float4 f = *reinterpret_cast<const float4*>(
                B + (size_t)(kk + r) * ldb + (bn + c));
            float xv[4] = {f.x, f.y, f.z, f.w};
            #pragma unroll
            for (int j = 0; j < 4; j++) {
                __nv_bfloat16 h = __float2bfloat16(xv[j]);
                sBh[r][c + j] = h;
                sBl[r][c + j] = __float2bfloat16(xv[j] - __bfloat162float(h));
            }
        }
        __syncthreads();

        uint32_t ah[MI][4], al[MI][4], bh[NI][2], bl[NI][2];
        #pragma unroll
        for (int mi = 0; mi < MI; mi++) {
            int row = wm + mi * 16 + (lane & 15);
            int col = (lane >> 4) * 8;
            ldm_x4(ah[mi], smem_u32(&sAh[row][col]));
            ldm_x4(al[mi], smem_u32(&sAl[row][col]));
        }
        #pragma unroll
        for (int ni = 0; ni < NI; ni++) {
            int row = lane & 15;
            int col = wn + ni * 8;
            ldm_x2t(bh[ni], smem_u32(&sBh[row][col]));
            ldm_x2t(bl[ni], smem_u32(&sBl[row][col]));
        }
        #pragma unroll
        for (int mi = 0; mi < MI; mi++)
            #pragma unroll
            for (int ni = 0; ni < NI; ni++) {
                mma_bf16(acc[mi][ni], ah[mi], bh[ni]);
                mma_bf16(acc[mi][ni], ah[mi], bl[ni]);
                mma_bf16(acc[mi][ni], al[mi], bh[ni]);
            }
        __syncthreads();
    }

    #pragma unroll
    for (int mi = 0; mi < MI; mi++) {
        #pragma unroll
        for (int ni = 0; ni < NI; ni++) {
            int row = bm + wm + mi * 16 + (lane >> 2);
            int col = bn + wn + ni * 8 + (lane & 3) * 2;
            float b0 = 0.f, b1 = 0.f;
            if (bias) { b0 = bias[col]; b1 = bias[col + 1]; }
            if (row < M) {
                C[(size_t)row * ldc + col]     = acc[mi][ni][0] + b0;
                C[(size_t)row * ldc + col + 1] = acc[mi][ni][1] + b1;
            }
            if (row + 8 < M) {
                C[(size_t)(row + 8) * ldc + col]     = acc[mi][ni][2] + b0;
                C[(size_t)(row + 8) * ldc + col + 1] = acc[mi][ni][3] + b1;
            }
        }
    }
}

// ================= persistent recurrence kernel ================================
struct Smem {
    __nv_bfloat16 A[2][2][64][40];   // [buf][hi/lo][row][col] — 20480 B
    __nv_bfloat16 B[2][2][32][40];   //                        — 10240 B
};

__device__ __forceinline__ void grid_sync() {
    __syncthreads();
    if (threadIdx.x == 0) {
        unsigned g = atomicAdd(&g_bar_gen, 0u);
        __threadfence();
        unsigned prev = atomicAdd(&g_bar_cnt, 1u);
        if (prev == NCTA - 1) {
            atomicExch(&g_bar_cnt, 0u);
            __threadfence();
            atomicAdd(&g_bar_gen, 1u);
        } else {
            while (atomicAdd(&g_bar_gen, 0u) == g) { }
        }
        __threadfence();
    }
    __syncthreads();
}

// One 64xBN tile, full K=2048, A/B pre-split bf16 hi/lo, double-buffered smem.
// NI=2 -> BN=32 (B loaders: tid<128); NI=1 -> BN=16 (B loaders: tid<64).
template <int NI>
__device__ __forceinline__ void gemm64(
    Smem& sm,
    const __nv_bfloat16* __restrict__ Ah, const __nv_bfloat16* __restrict__ Al,
    const __nv_bfloat16* __restrict__ Bh, const __nv_bfloat16* __restrict__ Bl,
    int ldb, int bn, float acc[2][4])
{
    const int tid  = threadIdx.x;
    const int lane = tid & 31;
    const int warp = tid >> 5;
    const int wm   = (warp & 3) * 16;
    const int wn   = (warp >> 2) * (NI * 8);
    const int ar   = tid >> 2;
    const int ac   = (tid & 3) * 8;
    const int rb   = (NI == 2) ? (tid >> 2) : (tid >> 1);
    const int cb   = (NI == 2) ? ((tid & 3) * 8) : ((tid & 1) * 8);
    const bool bact = tid < (NI == 2 ? 128 : 64);

    uint4 ra_h, ra_l;
    uint4 rb_h = make_uint4(0, 0, 0, 0), rb_l = make_uint4(0, 0, 0, 0);

    auto prefetch = [&](int kk) {
        ra_h = *reinterpret_cast<const uint4*>(Ah + (size_t)ar * HD + kk + ac);
        ra_l = *reinterpret_cast<const uint4*>(Al + (size_t)ar * HD + kk + ac);
        if (bact) {
            size_t off = (size_t)(kk + rb) * ldb + bn + cb;
            rb_h = *reinterpret_cast<const uint4*>(Bh + off);
            rb_l = *reinterpret_cast<const uint4*>(Bl + off);
        }
    };
    auto stage = [&](int buf) {
        *reinterpret_cast<uint4*>(&sm.A[buf][0][ar][ac]) = ra_h;
        *reinterpret_cast<uint4*>(&sm.A[buf][1][ar][ac]) = ra_l;
        if (bact) {
            *reinterpret_cast<uint4*>(&sm.B[buf][0][rb][cb]) = rb_h;
            *reinterpret_cast<uint4*>(&sm.B[buf][1][rb][cb]) = rb_l;
        }
    };

    prefetch(0);
    stage(0);
    __syncthreads();

    int buf = 0;
    #pragma unroll 1
    for (int kk = 0; kk < HD; kk += 32) {
        const bool more = (kk + 32 < HD);
        if (more) prefetch(kk + 32);
        #pragma unroll
        for (int ks = 0; ks < 2; ks++) {
            uint32_t ahf[4], alf[4];
            ldm_x4(ahf, smem_u32(&sm.A[buf][0][wm + (lane & 15)][ks * 16 + (lane >> 4) * 8]));
            ldm_x4(alf, smem_u32(&sm.A[buf][1][wm + (lane & 15)][ks * 16 + (lane >> 4) * 8]));
            #pragma unroll
            for (int ni = 0; ni < NI; ni++) {
                uint32_t bhf[2], blf[2];
                ldm_x2t(bhf, smem_u32(&sm.B[buf][0][ks * 16 + (lane & 15)][wn + ni * 8]));
                ldm_x2t(blf, smem_u32(&sm.B[buf][1][ks * 16 + (lane & 15)][wn + ni * 8]));
                mma_bf16(acc[ni], ahf, bhf);
                mma_bf16(acc[ni], ahf, blf);
                mma_bf16(acc[ni], alf, bhf);
            }
        }
        if (more) stage(buf ^ 1);
        __syncthreads();
        buf ^= 1;
    }
}

__global__ void __launch_bounds__(256, 1) gru_scan() {
    __shared__ __align__(16) Smem sm;
    const int tid  = threadIdx.x;
    const int lane = tid & 31;
    const int warp = tid >> 5;
    const int wm   = (warp & 3) * 16;
    const int cta  = blockIdx.x;

    #pragma unroll 1
    for (int t = 0; t < T_STEPS; t++) {
        const float* xg = g_XG + (size_t)t * NB * (3 * HD);
        const float* Ht = g_Hall + (size_t)t * NB * HD;

        // ---- GEMM1: pre-acts for [z|r], columns [cta*32, cta*32+32) of 4096
        {
            float acc[2][4] = {{0.f,0.f,0.f,0.f},{0.f,0.f,0.f,0.f}};
            gemm64<2>(sm, g_H_hi, g_H_lo, g_Wzr_hi, g_Wzr_lo, 2 * HD, cta * 32, acc);

            const bool is_r  = (cta >= 64);
            const int  nbase = (is_r ? (cta - 64) : cta) * 32;
            const int  wn    = (warp >> 2) * 16;
            const int  r0    = wm + (lane >> 2);
            #pragma unroll
            for (int ni = 0; ni < 2; ni++) {
                const int c = wn + ni * 8 + (lane & 3) * 2;
                #pragma unroll
                for (int half = 0; half < 2; half++) {
                    const int r = r0 + half * 8;
                    #pragma unroll
                    for (int j = 0; j < 2; j++) {
                        const int n = nbase + c + j;
                        float pre = acc[ni][half * 2 + j] +
                                    xg[(size_t)r * (3 * HD) + (is_r ? HD : 0) + n];
                        float v = sigmoidf_(pre);
                        if (!is_r) {
                            g_Z[r * HD + n] = v;
                        } else {
                            float h  = Ht[(size_t)r * HD + n];
                            float rh = v * h;
                            __nv_bfloat16 hi = __float2bfloat16(rh);
                            g_RH_hi[r * HD + n] = hi;
                            g_RH_lo[r * HD + n] =
                                __float2bfloat16(rh - __bfloat162float(hi));
                        }
                    }
                }
            }
        }
        grid_sync();

        // ---- GEMM2: h-candidate pre-acts, columns [cta*16, cta*16+16) of 2048
        {
            float acc[2][4] = {{0.f,0.f,0.f,0.f},{0.f,0.f,0.f,0.f}};
            gemm64<1>(sm, g_RH_hi, g_RH_lo, g_Whh_hi, g_Whh_lo, HD, cta * 16, acc);

            const int wn = (warp >> 2) * 8;
            const int r0 = wm + (lane >> 2);
            const int c  = wn + (lane & 3) * 2;
            #pragma unroll
            for (int half = 0; half < 2; half++) {
                const int r = r0 + half * 8;
                #pragma unroll
                for (int j = 0; j < 2; j++) {
                    const int n = cta * 16 + c + j;
                    float pre = acc[0][half * 2 + j] +
                                xg[(size_t)r * (3 * HD) + 2 * HD + n];
                    float ht = tanhf(pre);
                    float z  = g_Z[r * HD + n];
                    float h  = Ht[(size_t)r * HD + n];
                    float hn = z * h + (1.f - z) * ht;
                    g_Hall[((size_t)(t + 1) * NB + r) * HD + n] = hn;
                    __nv_bfloat16 hi = __float2bfloat16(hn);
                    g_H_hi[r * HD + n] = hi;
                    g_H_lo[r * HD + n] = __float2bfloat16(hn - __bfloat162float(hi));
                }
            }
        }
        grid_sync();
    }
}

// ================= setup / copy kernels =======================================
__global__ void prep_weights(const float* __restrict__ Whz,
                             const float* __restrict__ Whr,
                             const float* __restrict__ Whh) {
    size_t i = (size_t)blockIdx.x * blockDim.x + threadIdx.x;
    if (i >= (size_t)HD * HD) return;
    size_t k = i / HD, n = i % HD;
    float z = Whz[i];
    __nv_bfloat16 zh = __float2bfloat16(z);
    g_Wzr_hi[k * (2 * HD) + n] = zh;
    g_Wzr_lo[k * (2 * HD) + n] = __float2bfloat16(z - __bfloat162float(zh));
    float r = Whr[i];
    __nv_bfloat16 rh = __float2bfloat16(r);
    g_Wzr_hi[k * (2 * HD) + HD + n] = rh;
    g_Wzr_lo[k * (2 * HD) + HD + n] = __float2bfloat16(r - __bfloat162float(rh));
    float w = Whh[i];
    __nv_bfloat16 wh = __float2bfloat16(w);
    g_Whh_hi[i] = wh;
    g_Whh_lo[i] = __float2bfloat16(w - __bfloat162float(wh));
}

__global__ void prep_state(const float* __restrict__ state) {
    int i = blockIdx.x * blockDim.x + threadIdx.x;
    if (i >= NB * HD) return;
    float h = state[i];
    g_Hall[i] = h;
    __nv_bfloat16 hi = __float2bfloat16(h);
    g_H_hi[i] = hi;
    g_H_lo[i] = __float2bfloat16(h - __bfloat162float(hi));
}

__global__ void copy_hfinal(float* __restrict__ dst) {
    int i = blockIdx.x * blockDim.x + threadIdx.x;
    if (i >= NB * HD) return;
    dst[i] = g_Hall[(size_t)T_STEPS * NB * HD + i];
}

// ================= launch ======================================================
extern "C" void kernel_launch(void* const* d_in, const int* in_sizes, int n_in,
                              void* d_out, int out_size) {
    const float* X     = (const float*)d_in[0];
    const float* state = (const float*)d_in[1];
    const float* W_xz  = (const float*)d_in[2];
    const float* W_hz  = (const float*)d_in[3];
    const float* b_z   = (const float*)d_in[4];
    const float* W_xr  = (const float*)d_in[5];
    const float* W_hr  = (const float*)d_in[6];
    const float* b_r   = (const float*)d_in[7];
    const float* W_xh  = (const float*)d_in[8];
    const float* W_hh  = (const float*)d_in[9];
    const float* b_h   = (const float*)d_in[10];
    const float* W_hq  = (const float*)d_in[11];
    const float* b_hq  = (const float*)d_in[12];
    float* out = (float*)d_out;

    float* pXG;
    float* pHall;
    cudaGetSymbolAddress((void**)&pXG,   g_XG);
    cudaGetSymbolAddress((void**)&pHall, g_Hall);

    // Setup: weight split + H_0
    prep_weights<<<(int)(((size_t)HD * HD + 255) / 256), 256>>>(W_hz, W_hr, W_hh);
    prep_state<<<(NB * HD + 255) / 256, 256>>>(state);

    // Phase A: XG[:, g*HD:(g+1)*HD] = X @ W_xg + b_g (parallel over all t)
    {
        dim3 grid(HD / 128, TBM / 128, 1);
        gemm_split3<128, 128, 64, 32><<<grid, 256>>>(X, ID, W_xz, HD,
            pXG + 0 * HD, 3 * HD, TBM, HD, ID, b_z);
        gemm_split3<128, 128, 64, 32><<<grid, 256>>>(X, ID, W_xr, HD,
            pXG + 1 * HD, 3 * HD, TBM, HD, ID, b_r);
        gemm_split3<128, 128, 64, 32><<<grid, 256>>>(X, ID, W_xh, HD,
            pXG + 2 * HD, 3 * HD, TBM, HD, ID, b_h);
    }

    // Phase B: entire 512-step recurrence in ONE persistent kernel
    gru_scan<<<NCTA, 256>>>();

    // Phase C: Y[t*B+b, :] = H_{t+1}[b, :] @ W_hq + b_hq (one big GEMM)
    gemm_split3<128, 128, 64, 32><<<dim3(ID / 128, TBM / 128, 1), 256>>>(
        pHall + (size_t)NB * HD, HD, W_hq, ID, out, ID,
        TBM, ID, HD, b_hq);

    // H_final (second tuple output) appended after Y
    if (out_size >= (int)((size_t)TBM * ID + (size_t)NB * HD)) {
        copy_hfinal<<<(NB * HD + 255) / 256, 256>>>(out + (size_t)TBM * ID);
    }
}

// round 16
// speedup vs baseline: 1.0006x; 1.0006x over previous
#include <cuda_runtime.h>
#include <cuda_bf16.h>
#include <cstdint>
#include <math.h>

// Problem dims (fixed by the reference)
constexpr int T_STEPS = 512;
constexpr int NB      = 64;     // batch
constexpr int ID      = 1024;   // input dim
constexpr int HD      = 2048;   // hidden dim
constexpr int TBM     = T_STEPS * NB;   // 32768 rows
constexpr int NCTA    = 128;    // persistent-kernel grid (<= 148 SMs -> co-resident)

// ---------------- scratch (device globals; no cudaMalloc allowed) ------------
__device__ float g_XG  [(size_t)TBM * 3 * HD];            // X@Wx{z,r,h}+b  (TB, 6144)
__device__ float g_Hall[(size_t)(T_STEPS + 1) * NB * HD]; // H_0..H_T (fp32 history)
__device__ float g_Z   [NB * HD];                          // Z gate (fp32)

__device__ __nv_bfloat16 g_Wzr_hi[(size_t)HD * 2 * HD];    // [W_hz|W_hr] bf16 hi
__device__ __nv_bfloat16 g_Wzr_lo[(size_t)HD * 2 * HD];    //              bf16 lo
__device__ __nv_bfloat16 g_Whh_hi[(size_t)HD * HD];
__device__ __nv_bfloat16 g_Whh_lo[(size_t)HD * HD];
__device__ __nv_bfloat16 g_H_hi [NB * HD];                 // current H (bf16 split)
__device__ __nv_bfloat16 g_H_lo [NB * HD];
__device__ __nv_bfloat16 g_RH_hi[NB * HD];                 // R*H (bf16 split)
__device__ __nv_bfloat16 g_RH_lo[NB * HD];

__device__ unsigned g_bar_cnt = 0;
__device__ unsigned g_bar_gen = 0;

// ---------------- mma helpers ------------------------------------------------
__device__ __forceinline__ uint32_t smem_u32(const void* p) {
    return (uint32_t)__cvta_generic_to_shared(p);
}
__device__ __forceinline__ void ldm_x4(uint32_t* r, uint32_t a) {
    asm volatile("ldmatrix.sync.aligned.m8n8.x4.shared.b16 {%0,%1,%2,%3}, [%4];"
                 : "=r"(r[0]), "=r"(r[1]), "=r"(r[2]), "=r"(r[3]) : "r"(a));
}
__device__ __forceinline__ void ldm_x2t(uint32_t* r, uint32_t a) {
    asm volatile("ldmatrix.sync.aligned.m8n8.x2.trans.shared.b16 {%0,%1}, [%2];"
                 : "=r"(r[0]), "=r"(r[1]) : "r"(a));
}
__device__ __forceinline__ void mma_bf16(float* c, const uint32_t* a, const uint32_t* b) {
    asm volatile("mma.sync.aligned.m16n8k16.row.col.f32.bf16.bf16.f32 "
                 "{%0,%1,%2,%3}, {%4,%5,%6,%7}, {%8,%9}, {%0,%1,%2,%3};"
                 : "+f"(c[0]), "+f"(c[1]), "+f"(c[2]), "+f"(c[3])
                 : "r"(a[0]), "r"(a[1]), "r"(a[2]), "r"(a[3]),
                   "r"(b[0]), "r"(b[1]));
}
__device__ __forceinline__ float sigmoidf_(float x) { return 1.f / (1.f + __expf(-x)); }

// ================= big GEMM (phases A & C) — proven template ==================
// C = A(MxK) @ B(KxN) + bias, fp32 in/out, bf16 split-3 tensor-core compute.
template <int BM, int BN, int WM, int WN>
__global__ void __launch_bounds__(32 * (BM / WM) * (BN / WN))
gemm_split3(const float* __restrict__ A, int lda,
            const float* __restrict__ B, int ldb,
            float* __restrict__ C, int ldc,
            int M, int N, int K_total,
            const float* __restrict__ bias)
{
    constexpr int BK      = 16;
    constexpr int WARPS_M = BM / WM;
    constexpr int WARPS_N = BN / WN;
    constexpr int THREADS = 32 * WARPS_M * WARPS_N;
    constexpr int MI = WM / 16, NI = WN / 8;
    constexpr int LDA_S = BK + 8;
    constexpr int LDB_S = BN + 8;

    __shared__ __align__(16) __nv_bfloat16 sAh[BM][LDA_S];
    __shared__ __align__(16) __nv_bfloat16 sAl[BM][LDA_S];
    __shared__ __align__(16) __nv_bfloat16 sBh[BK][LDB_S];
    __shared__ __align__(16) __nv_bfloat16 sBl[BK][LDB_S];

    const int tid  = threadIdx.x;
    const int lane = tid & 31;
    const int warp = tid >> 5;
    const int wm   = (warp % WARPS_M) * WM;
    const int wn   = (warp / WARPS_M) * WN;
    const int bm   = blockIdx.y * BM;
    const int bn   = blockIdx.x * BN;

    float acc[MI][NI][4];
    #pragma unroll
    for (int mi = 0; mi < MI; mi++)
        #pragma unroll
        for (int ni = 0; ni < NI; ni++)
            #pragma unroll
            for (int j = 0; j < 4; j++) acc[mi][ni][j] = 0.f;

    constexpr int A_V = (BM * BK) / (THREADS * 4);
    constexpr int B_V = (BK * BN) / (THREADS * 4);

    for (int kk = 0; kk < K_total; kk += BK) {
        #pragma unroll
        for (int v = 0; v < A_V; v++) {
            int linear = (tid + v * THREADS) * 4;
            int r = linear / BK, c = linear % BK;
            float4 f = make_float4(0.f, 0.f, 0.f, 0.f);
            int gr = bm + r;
            if (gr < M)
                f = *reinterpret_cast<const float4*>(A + (size_t)gr * lda + (kk + c));
            float xv[4] = {f.x, f.y, f.z, f.w};
            #pragma unroll
            for (int j = 0; j < 4; j++) {
                __nv_bfloat16 h = __float2bfloat16(xv[j]);
                sAh[r][c + j] = h;
                sAl[r][c + j] = __float2bfloat16(xv[j] - __bfloat162float(h));
            }
        }
        #pragma unroll
        for (int v = 0; v < B_V; v++) {
            int linear = (tid + v * THREADS) * 4;
            int r = linear / BN, c = linear % BN;
            float4 f = *reinterpret_cast<const float4*>(
                B + (size_t)(kk + r) * ldb + (bn + c));
            float xv[4] = {f.x, f.y, f.z, f.w};
            #pragma unroll
            for (int j = 0; j < 4; j++) {
                __nv_bfloat16 h = __float2bfloat16(xv[j]);
                sBh[r][c + j] = h;
                sBl[r][c + j] = __float2bfloat16(xv[j] - __bfloat162float(h));
            }
        }
        __syncthreads();

        uint32_t ah[MI][4], al[MI][4], bh[NI][2], bl[NI][2];
        #pragma unroll
        for (int mi = 0; mi < MI; mi++) {
            int row = wm + mi * 16 + (lane & 15);
            int col = (lane >> 4) * 8;
            ldm_x4(ah[mi], smem_u32(&sAh[row][col]));
            ldm_x4(al[mi], smem_u32(&sAl[row][col]));
        }
        #pragma unroll
        for (int ni = 0; ni < NI; ni++) {
            int row = lane & 15;
            int col = wn + ni * 8;
            ldm_x2t(bh[ni], smem_u32(&sBh[row][col]));
            ldm_x2t(bl[ni], smem_u32(&sBl[row][col]));
        }
        #pragma unroll
        for (int mi = 0; mi < MI; mi++)
            #pragma unroll
            for (int ni = 0; ni < NI; ni++) {
                mma_bf16(acc[mi][ni], ah[mi], bh[ni]);
                mma_bf16(acc[mi][ni], ah[mi], bl[ni]);
                mma_bf16(acc[mi][ni], al[mi], bh[ni]);
            }
        __syncthreads();
    }

    #pragma unroll
    for (int mi = 0; mi < MI; mi++) {
        #pragma unroll
        for (int ni = 0; ni < NI; ni++) {
            int row = bm + wm + mi * 16 + (lane >> 2);
            int col = bn + wn + ni * 8 + (lane & 3) * 2;
            float b0 = 0.f, b1 = 0.f;
            if (bias) { b0 = bias[col]; b1 = bias[col + 1]; }
            if (row < M) {
                C[(size_t)row * ldc + col]     = acc[mi][ni][0] + b0;
                C[(size_t)row * ldc + col + 1] = acc[mi][ni][1] + b1;
            }
            if (row + 8 < M) {
                C[(size_t)(row + 8) * ldc + col]     = acc[mi][ni][2] + b0;
                C[(size_t)(row + 8) * ldc + col + 1] = acc[mi][ni][3] + b1;
            }
        }
    }
}

// ================= persistent recurrence kernel ================================
struct Smem {
    __nv_bfloat16 A[2][2][64][40];   // [buf][hi/lo][row][col] — 20480 B
    __nv_bfloat16 B[2][2][32][40];   //                        — 10240 B
};

__device__ __forceinline__ void grid_sync() {
    __syncthreads();
    if (threadIdx.x == 0) {
        unsigned g = atomicAdd(&g_bar_gen, 0u);
        __threadfence();
        unsigned prev = atomicAdd(&g_bar_cnt, 1u);
        if (prev == NCTA - 1) {
            atomicExch(&g_bar_cnt, 0u);
            __threadfence();
            atomicAdd(&g_bar_gen, 1u);
        } else {
            while (atomicAdd(&g_bar_gen, 0u) == g) { }
        }
        __threadfence();
    }
    __syncthreads();
}

// One 64xBN tile, full K=2048, A/B pre-split bf16 hi/lo, double-buffered smem.
// NI=2 -> BN=32 (B loaders: tid<128); NI=1 -> BN=16 (B loaders: tid<64).
template <int NI>
__device__ __forceinline__ void gemm64(
    Smem& sm,
    const __nv_bfloat16* __restrict__ Ah, const __nv_bfloat16* __restrict__ Al,
    const __nv_bfloat16* __restrict__ Bh, const __nv_bfloat16* __restrict__ Bl,
    int ldb, int bn, float acc[2][4])
{
    const int tid  = threadIdx.x;
    const int lane = tid & 31;
    const int warp = tid >> 5;
    const int wm   = (warp & 3) * 16;
    const int wn   = (warp >> 2) * (NI * 8);
    const int ar   = tid >> 2;
    const int ac   = (tid & 3) * 8;
    const int rb   = (NI == 2) ? (tid >> 2) : (tid >> 1);
    const int cb   = (NI == 2) ? ((tid & 3) * 8) : ((tid & 1) * 8);
    const bool bact = tid < (NI == 2 ? 128 : 64);

    uint4 ra_h, ra_l;
    uint4 rb_h = make_uint4(0, 0, 0, 0), rb_l = make_uint4(0, 0, 0, 0);

    auto prefetch = [&](int kk) {
        ra_h = *reinterpret_cast<const uint4*>(Ah + (size_t)ar * HD + kk + ac);
        ra_l = *reinterpret_cast<const uint4*>(Al + (size_t)ar * HD + kk + ac);
        if (bact) {
            size_t off = (size_t)(kk + rb) * ldb + bn + cb;
            rb_h = *reinterpret_cast<const uint4*>(Bh + off);
            rb_l = *reinterpret_cast<const uint4*>(Bl + off);
        }
    };
    auto stage = [&](int buf) {
        *reinterpret_cast<uint4*>(&sm.A[buf][0][ar][ac]) = ra_h;
        *reinterpret_cast<uint4*>(&sm.A[buf][1][ar][ac]) = ra_l;
        if (bact) {
            *reinterpret_cast<uint4*>(&sm.B[buf][0][rb][cb]) = rb_h;
            *reinterpret_cast<uint4*>(&sm.B[buf][1][rb][cb]) = rb_l;
        }
    };

    prefetch(0);
    stage(0);
    __syncthreads();

    int buf = 0;
    #pragma unroll 1
    for (int kk = 0; kk < HD; kk += 32) {
        const bool more = (kk + 32 < HD);
        if (more) prefetch(kk + 32);
        #pragma unroll
        for (int ks = 0; ks < 2; ks++) {
            uint32_t ahf[4], alf[4];
            ldm_x4(ahf, smem_u32(&sm.A[buf][0][wm + (lane & 15)][ks * 16 + (lane >> 4) * 8]));
            ldm_x4(alf, smem_u32(&sm.A[buf][1][wm + (lane & 15)][ks * 16 + (lane >> 4) * 8]));
            #pragma unroll
            for (int ni = 0; ni < NI; ni++) {
                uint32_t bhf[2], blf[2];
                ldm_x2t(bhf, smem_u32(&sm.B[buf][0][ks * 16 + (lane & 15)][wn + ni * 8]));
                ldm_x2t(blf, smem_u32(&sm.B[buf][1][ks * 16 + (lane & 15)][wn + ni * 8]));
                mma_bf16(acc[ni], ahf, bhf);
                mma_bf16(acc[ni], ahf, blf);
                mma_bf16(acc[ni], alf, bhf);
            }
        }
        if (more) stage(buf ^ 1);
        __syncthreads();
        buf ^= 1;
    }
}

__global__ void __launch_bounds__(256, 1) gru_scan() {
    __shared__ __align__(16) Smem sm;
    const int tid  = threadIdx.x;
    const int lane = tid & 31;
    const int warp = tid >> 5;
    const int wm   = (warp & 3) * 16;
    const int cta  = blockIdx.x;

    #pragma unroll 1
    for (int t = 0; t < T_STEPS; t++) {
        const float* xg = g_XG + (size_t)t * NB * (3 * HD);
        const float* Ht = g_Hall + (size_t)t * NB * HD;

        // ---- GEMM1: pre-acts for [z|r], columns [cta*32, cta*32+32) of 4096
        {
            float acc[2][4] = {{0.f,0.f,0.f,0.f},{0.f,0.f,0.f,0.f}};
            gemm64<2>(sm, g_H_hi, g_H_lo, g_Wzr_hi, g_Wzr_lo, 2 * HD, cta * 32, acc);

            const bool is_r  = (cta >= 64);
            const int  nbase = (is_r ? (cta - 64) : cta) * 32;
            const int  wn    = (warp >> 2) * 16;
            const int  r0    = wm + (lane >> 2);
            #pragma unroll
            for (int ni = 0; ni < 2; ni++) {
                const int c = wn + ni * 8 + (lane & 3) * 2;
                #pragma unroll
                for (int half = 0; half < 2; half++) {
                    const int r = r0 + half * 8;
                    #pragma unroll
                    for (int j = 0; j < 2; j++) {
                        const int n = nbase + c + j;
                        float pre = acc[ni][half * 2 + j] +
                                    xg[(size_t)r * (3 * HD) + (is_r ? HD : 0) + n];
                        float v = sigmoidf_(pre);
                        if (!is_r) {
                            g_Z[r * HD + n] = v;
                        } else {
                            float h  = Ht[(size_t)r * HD + n];
                            float rh = v * h;
                            __nv_bfloat16 hi = __float2bfloat16(rh);
                            g_RH_hi[r * HD + n] = hi;
                            g_RH_lo[r * HD + n] =
                                __float2bfloat16(rh - __bfloat162float(hi));
                        }
                    }
                }
            }
        }
        grid_sync();

        // ---- GEMM2: h-candidate pre-acts, columns [cta*16, cta*16+16) of 2048
        {
            float acc[2][4] = {{0.f,0.f,0.f,0.f},{0.f,0.f,0.f,0.f}};
            gemm64<1>(sm, g_RH_hi, g_RH_lo, g_Whh_hi, g_Whh_lo, HD, cta * 16, acc);

            const int wn = (warp >> 2) * 8;
            const int r0 = wm + (lane >> 2);
            const int c  = wn + (lane & 3) * 2;
            #pragma unroll
            for (int half = 0; half < 2; half++) {
                const int r = r0 + half * 8;
                #pragma unroll
                for (int j = 0; j < 2; j++) {
                    const int n = cta * 16 + c + j;
                    float pre = acc[0][half * 2 + j] +
                                xg[(size_t)r * (3 * HD) + 2 * HD + n];
                    float ht = tanhf(pre);
                    float z  = g_Z[r * HD + n];
                    float h  = Ht[(size_t)r * HD + n];
                    float hn = z * h + (1.f - z) * ht;
                    g_Hall[((size_t)(t + 1) * NB + r) * HD + n] = hn;
                    __nv_bfloat16 hi = __float2bfloat16(hn);
                    g_H_hi[r * HD + n] = hi;
                    g_H_lo[r * HD + n] = __float2bfloat16(hn - __bfloat162float(hi));
                }
            }
        }
        grid_sync();
    }
}

// ================= setup / copy kernels =======================================
__global__ void prep_weights(const float* __restrict__ Whz,
                             const float* __restrict__ Whr,
                             const float* __restrict__ Whh) {
    size_t i = (size_t)blockIdx.x * blockDim.x + threadIdx.x;
    if (i >= (size_t)HD * HD) return;
    size_t k = i / HD, n = i % HD;
    float z = Whz[i];
    __nv_bfloat16 zh = __float2bfloat16(z);
    g_Wzr_hi[k * (2 * HD) + n] = zh;
    g_Wzr_lo[k * (2 * HD) + n] = __float2bfloat16(z - __bfloat162float(zh));
    float r = Whr[i];
    __nv_bfloat16 rh = __float2bfloat16(r);
    g_Wzr_hi[k * (2 * HD) + HD + n] = rh;
    g_Wzr_lo[k * (2 * HD) + HD + n] = __float2bfloat16(r - __bfloat162float(rh));
    float w = Whh[i];
    __nv_bfloat16 wh = __float2bfloat16(w);
    g_Whh_hi[i] = wh;
    g_Whh_lo[i] = __float2bfloat16(w - __bfloat162float(wh));
}

__global__ void prep_state(const float* __restrict__ state) {
    int i = blockIdx.x * blockDim.x + threadIdx.x;
    if (i >= NB * HD) return;
    float h = state[i];
    g_Hall[i] = h;
    __nv_bfloat16 hi = __float2bfloat16(h);
    g_H_hi[i] = hi;
    g_H_lo[i] = __float2bfloat16(h - __bfloat162float(hi));
}

__global__ void copy_hfinal(float* __restrict__ dst) {
    int i = blockIdx.x * blockDim.x + threadIdx.x;
    if (i >= NB * HD) return;
    dst[i] = g_Hall[(size_t)T_STEPS * NB * HD + i];
}

// ================= launch ======================================================
extern "C" void kernel_launch(void* const* d_in, const int* in_sizes, int n_in,
                              void* d_out, int out_size) {
    const float* X     = (const float*)d_in[0];
    const float* state = (const float*)d_in[1];
    const float* W_xz  = (const float*)d_in[2];
    const float* W_hz  = (const float*)d_in[3];
    const float* b_z   = (const float*)d_in[4];
    const float* W_xr  = (const float*)d_in[5];
    const float* W_hr  = (const float*)d_in[6];
    const float* b_r   = (const float*)d_in[7];
    const float* W_xh  = (const float*)d_in[8];
    const float* W_hh  = (const float*)d_in[9];
    const float* b_h   = (const float*)d_in[10];
    const float* W_hq  = (const float*)d_in[11];
    const float* b_hq  = (const float*)d_in[12];
    float* out = (float*)d_out;

    float* pXG;
    float* pHall;
    cudaGetSymbolAddress((void**)&pXG,   g_XG);
    cudaGetSymbolAddress((void**)&pHall, g_Hall);

    // Setup: weight split + H_0
    prep_weights<<<(int)(((size_t)HD * HD + 255) / 256), 256>>>(W_hz, W_hr, W_hh);
    prep_state<<<(NB * HD + 255) / 256, 256>>>(state);

    // Phase A: XG[:, g*HD:(g+1)*HD] = X @ W_xg + b_g (parallel over all t)
    {
        dim3 grid(HD / 128, TBM / 128, 1);
        gemm_split3<128, 128, 64, 32><<<grid, 256>>>(X, ID, W_xz, HD,
            pXG + 0 * HD, 3 * HD, TBM, HD, ID, b_z);
        gemm_split3<128, 128, 64, 32><<<grid, 256>>>(X, ID, W_xr, HD,
            pXG + 1 * HD, 3 * HD, TBM, HD, ID, b_r);
        gemm_split3<128, 128, 64, 32><<<grid, 256>>>(X, ID, W_xh, HD,
            pXG + 2 * HD, 3 * HD, TBM, HD, ID, b_h);
    }

    // Phase B: entire 512-step recurrence in ONE persistent kernel
    gru_scan<<<NCTA, 256>>>();

    // Phase C: Y[t*B+b, :] = H_{t+1}[b, :] @ W_hq + b_hq (one big GEMM)
    gemm_split3<128, 128, 64, 32><<<dim3(ID / 128, TBM / 128, 1), 256>>>(
        pHall + (size_t)NB * HD, HD, W_hq, ID, out, ID,
        TBM, ID, HD, b_hq);

    // H_final (second tuple output) appended after Y
    if (out_size >= (int)((size_t)TBM * ID + (size_t)NB * HD)) {
        copy_hfinal<<<(NB * HD + 255) / 256, 256>>>(out + (size_t)TBM * ID);
    }
}

// round 17
// speedup vs baseline: 1.0018x; 1.0012x over previous
#include <cuda_runtime.h>
#include <cuda_bf16.h>
#include <cstdint>
#include <math.h>

// Problem dims (fixed by the reference)
constexpr int T_STEPS = 512;
constexpr int NB      = 64;     // batch
constexpr int ID      = 1024;   // input dim
constexpr int HD      = 2048;   // hidden dim
constexpr int TBM     = T_STEPS * NB;   // 32768 rows
constexpr int NCTA    = 128;    // persistent-kernel grid (<= 148 SMs -> co-resident)

// ---------------- scratch (device globals; no cudaMalloc allowed) ------------
__device__ float g_XG  [(size_t)TBM * 3 * HD];            // X@Wx{z,r,h}+b  (TB, 6144)
__device__ float g_Hall[(size_t)(T_STEPS + 1) * NB * HD]; // H_0..H_T (fp32 history)
__device__ float g_Z   [NB * HD];                          // Z gate (fp32)

__device__ __nv_bfloat16 g_Wzr_hi[(size_t)HD * 2 * HD];    // [W_hz|W_hr] bf16 hi
__device__ __nv_bfloat16 g_Wzr_lo[(size_t)HD * 2 * HD];    //              bf16 lo
__device__ __nv_bfloat16 g_Whh_hi[(size_t)HD * HD];
__device__ __nv_bfloat16 g_Whh_lo[(size_t)HD * HD];
__device__ __nv_bfloat16 g_H_hi [NB * HD];                 // current H (bf16 split)
__device__ __nv_bfloat16 g_H_lo [NB * HD];
__device__ __nv_bfloat16 g_RH_hi[NB * HD];                 // R*H (bf16 split)
__device__ __nv_bfloat16 g_RH_lo[NB * HD];

__device__ unsigned g_bar_cnt = 0;
__device__ unsigned g_bar_gen = 0;

// ---------------- mma helpers ------------------------------------------------
__device__ __forceinline__ uint32_t smem_u32(const void* p) {
    return (uint32_t)__cvta_generic_to_shared(p);
}
__device__ __forceinline__ void ldm_x4(uint32_t* r, uint32_t a) {
    asm volatile("ldmatrix.sync.aligned.m8n8.x4.shared.b16 {%0,%1,%2,%3}, [%4];"
                 : "=r"(r[0]), "=r"(r[1]), "=r"(r[2]), "=r"(r[3]) : "r"(a));
}
__device__ __forceinline__ void ldm_x2t(uint32_t* r, uint32_t a) {
    asm volatile("ldmatrix.sync.aligned.m8n8.x2.trans.shared.b16 {%0,%1}, [%2];"
                 : "=r"(r[0]), "=r"(r[1]) : "r"(a));
}
__device__ __forceinline__ void mma_bf16(float* c, const uint32_t* a, const uint32_t* b) {
    asm volatile("mma.sync.aligned.m16n8k16.row.col.f32.bf16.bf16.f32 "
                 "{%0,%1,%2,%3}, {%4,%5,%6,%7}, {%8,%9}, {%0,%1,%2,%3};"
                 : "+f"(c[0]), "+f"(c[1]), "+f"(c[2]), "+f"(c[3])
                 : "r"(a[0]), "r"(a[1]), "r"(a[2]), "r"(a[3]),
                   "r"(b[0]), "r"(b[1]));
}
__device__ __forceinline__ float sigmoidf_(float x) { return 1.f / (1.f + __expf(-x)); }

// ================= big GEMM (phases A & C) — proven template ==================
// C = A(MxK) @ B(KxN) + bias, fp32 in/out, bf16 split-3 tensor-core compute.
template <int BM, int BN, int WM, int WN>
__global__ void __launch_bounds__(32 * (BM / WM) * (BN / WN))
gemm_split3(const float* __restrict__ A, int lda,
            const float* __restrict__ B, int ldb,
            float* __restrict__ C, int ldc,
            int M, int N, int K_total,
            const float* __restrict__ bias)
{
    constexpr int BK      = 16;
    constexpr int WARPS_M = BM / WM;
    constexpr int WARPS_N = BN / WN;
    constexpr int THREADS = 32 * WARPS_M * WARPS_N;
    constexpr int MI = WM / 16, NI = WN / 8;
    constexpr int LDA_S = BK + 8;
    constexpr int LDB_S = BN + 8;

    __shared__ __align__(16) __nv_bfloat16 sAh[BM][LDA_S];
    __shared__ __align__(16) __nv_bfloat16 sAl[BM][LDA_S];
    __shared__ __align__(16) __nv_bfloat16 sBh[BK][LDB_S];
    __shared__ __align__(16) __nv_bfloat16 sBl[BK][LDB_S];

    const int tid  = threadIdx.x;
    const int lane = tid & 31;
    const int warp = tid >> 5;
    const int wm   = (warp % WARPS_M) * WM;
    const int wn   = (warp / WARPS_M) * WN;
    const int bm   = blockIdx.y * BM;
    const int bn   = blockIdx.x * BN;

    float acc[MI][NI][4];
    #pragma unroll
    for (int mi = 0; mi < MI; mi++)
        #pragma unroll
        for (int ni = 0; ni < NI; ni++)
            #pragma unroll
            for (int j = 0; j < 4; j++) acc[mi][ni][j] = 0.f;

    constexpr int A_V = (BM * BK) / (THREADS * 4);
    constexpr int B_V = (BK * BN) / (THREADS * 4);

    for (int kk = 0; kk < K_total; kk += BK) {
        #pragma unroll
        for (int v = 0; v < A_V; v++) {
            int linear = (tid + v * THREADS) * 4;
            int r = linear / BK, c = linear % BK;
            float4 f = make_float4(0.f, 0.f, 0.f, 0.f);
            int gr = bm + r;
            if (gr < M)
                f = *reinterpret_cast<const float4*>(A + (size_t)gr * lda + (kk + c));
            float xv[4] = {f.x, f.y, f.z, f.w};
            #pragma unroll
            for (int j = 0; j < 4; j++) {
                __nv_bfloat16 h = __float2bfloat16(xv[j]);
                sAh[r][c + j] = h;
                sAl[r][c + j] = __float2bfloat16(xv[j] - __bfloat162float(h));
            }
        }
        #pragma unroll
        for (int v = 0; v < B_V; v++) {
            int linear = (tid + v * THREADS) * 4;
            int r = linear / BN, c = linear % BN;
            float4 f = *reinterpret_cast<const float4*>(
                B + (size_t)(kk + r) * ldb + (bn + c));
            float xv[4] = {f.x, f.y, f.z, f.w};
            #pragma unroll
            for (int j = 0; j < 4; j++) {
                __nv_bfloat16 h = __float2bfloat16(xv[j]);
                sBh[r][c + j] = h;
                sBl[r][c + j] = __float2bfloat16(xv[j] - __bfloat162float(h));
            }
        }
        __syncthreads();

        uint32_t ah[MI][4], al[MI][4], bh[NI][2], bl[NI][2];
        #pragma unroll
        for (int mi = 0; mi < MI; mi++) {
            int row = wm + mi * 16 + (lane & 15);
            int col = (lane >> 4) * 8;
            ldm_x4(ah[mi], smem_u32(&sAh[row][col]));
            ldm_x4(al[mi], smem_u32(&sAl[row][col]));
        }
        #pragma unroll
        for (int ni = 0; ni < NI; ni++) {
            int row = lane & 15;
            int col = wn + ni * 8;
            ldm_x2t(bh[ni], smem_u32(&sBh[row][col]));
            ldm_x2t(bl[ni], smem_u32(&sBl[row][col]));
        }
        #pragma unroll
        for (int mi = 0; mi < MI; mi++)
            #pragma unroll
            for (int ni = 0; ni < NI; ni++) {
                mma_bf16(acc[mi][ni], ah[mi], bh[ni]);
                mma_bf16(acc[mi][ni], ah[mi], bl[ni]);
                mma_bf16(acc[mi][ni], al[mi], bh[ni]);
            }
        __syncthreads();
    }

    #pragma unroll
    for (int mi = 0; mi < MI; mi++) {
        #pragma unroll
        for (int ni = 0; ni < NI; ni++) {
            int row = bm + wm + mi * 16 + (lane >> 2);
            int col = bn + wn + ni * 8 + (lane & 3) * 2;
            float b0 = 0.f, b1 = 0.f;
            if (bias) { b0 = bias[col]; b1 = bias[col + 1]; }
            if (row < M) {
                C[(size_t)row * ldc + col]     = acc[mi][ni][0] + b0;
                C[(size_t)row * ldc + col + 1] = acc[mi][ni][1] + b1;
            }
            if (row + 8 < M) {
                C[(size_t)(row + 8) * ldc + col]     = acc[mi][ni][2] + b0;
                C[(size_t)(row + 8) * ldc + col + 1] = acc[mi][ni][3] + b1;
            }
        }
    }
}

// ================= persistent recurrence kernel ================================
struct Smem {
    __nv_bfloat16 A[2][2][64][40];   // [buf][hi/lo][row][col] — 20480 B
    __nv_bfloat16 B[2][2][32][40];   //                        — 10240 B
};

__device__ __forceinline__ void grid_sync() {
    __syncthreads();
    if (threadIdx.x == 0) {
        unsigned g = atomicAdd(&g_bar_gen, 0u);
        __threadfence();
        unsigned prev = atomicAdd(&g_bar_cnt, 1u);
        if (prev == NCTA - 1) {
            atomicExch(&g_bar_cnt, 0u);
            __threadfence();
            atomicAdd(&g_bar_gen, 1u);
        } else {
            while (atomicAdd(&g_bar_gen, 0u) == g) { }
        }
        __threadfence();
    }
    __syncthreads();
}

// One 64xBN tile, full K=2048, A/B pre-split bf16 hi/lo, double-buffered smem.
// NI=2 -> BN=32 (B loaders: tid<128); NI=1 -> BN=16 (B loaders: tid<64).
template <int NI>
__device__ __forceinline__ void gemm64(
    Smem& sm,
    const __nv_bfloat16* __restrict__ Ah, const __nv_bfloat16* __restrict__ Al,
    const __nv_bfloat16* __restrict__ Bh, const __nv_bfloat16* __restrict__ Bl,
    int ldb, int bn, float acc[2][4])
{
    const int tid  = threadIdx.x;
    const int lane = tid & 31;
    const int warp = tid >> 5;
    const int wm   = (warp & 3) * 16;
    const int wn   = (warp >> 2) * (NI * 8);
    const int ar   = tid >> 2;
    const int ac   = (tid & 3) * 8;
    const int rb   = (NI == 2) ? (tid >> 2) : (tid >> 1);
    const int cb   = (NI == 2) ? ((tid & 3) * 8) : ((tid & 1) * 8);
    const bool bact = tid < (NI == 2 ? 128 : 64);

    uint4 ra_h, ra_l;
    uint4 rb_h = make_uint4(0, 0, 0, 0), rb_l = make_uint4(0, 0, 0, 0);

    auto prefetch = [&](int kk) {
        ra_h = *reinterpret_cast<const uint4*>(Ah + (size_t)ar * HD + kk + ac);
        ra_l = *reinterpret_cast<const uint4*>(Al + (size_t)ar * HD + kk + ac);
        if (bact) {
            size_t off = (size_t)(kk + rb) * ldb + bn + cb;
            rb_h = *reinterpret_cast<const uint4*>(Bh + off);
            rb_l = *reinterpret_cast<const uint4*>(Bl + off);
        }
    };
    auto stage = [&](int buf) {
        *reinterpret_cast<uint4*>(&sm.A[buf][0][ar][ac]) = ra_h;
        *reinterpret_cast<uint4*>(&sm.A[buf][1][ar][ac]) = ra_l;
        if (bact) {
            *reinterpret_cast<uint4*>(&sm.B[buf][0][rb][cb]) = rb_h;
            *reinterpret_cast<uint4*>(&sm.B[buf][1][rb][cb]) = rb_l;
        }
    };

    prefetch(0);
    stage(0);
    __syncthreads();

    int buf = 0;
    #pragma unroll 1
    for (int kk = 0; kk < HD; kk += 32) {
        const bool more = (kk + 32 < HD);
        if (more) prefetch(kk + 32);
        #pragma unroll
        for (int ks = 0; ks < 2; ks++) {
            uint32_t ahf[4], alf[4];
            ldm_x4(ahf, smem_u32(&sm.A[buf][0][wm + (lane & 15)][ks * 16 + (lane >> 4) * 8]));
            ldm_x4(alf, smem_u32(&sm.A[buf][1][wm + (lane & 15)][ks * 16 + (lane >> 4) * 8]));
            #pragma unroll
            for (int ni = 0; ni < NI; ni++) {
                uint32_t bhf[2], blf[2];
                ldm_x2t(bhf, smem_u32(&sm.B[buf][0][ks * 16 + (lane & 15)][wn + ni * 8]));
                ldm_x2t(blf, smem_u32(&sm.B[buf][1][ks * 16 + (lane & 15)][wn + ni * 8]));
                mma_bf16(acc[ni], ahf, bhf);
                mma_bf16(acc[ni], ahf, blf);
                mma_bf16(acc[ni], alf, bhf);
            }
        }
        if (more) stage(buf ^ 1);
        __syncthreads();
        buf ^= 1;
    }
}

__global__ void __launch_bounds__(256, 1) gru_scan() {
    __shared__ __align__(16) Smem sm;
    const int tid  = threadIdx.x;
    const int lane = tid & 31;
    const int warp = tid >> 5;
    const int wm   = (warp & 3) * 16;
    const int cta  = blockIdx.x;

    #pragma unroll 1
    for (int t = 0; t < T_STEPS; t++) {
        const float* xg = g_XG + (size_t)t * NB * (3 * HD);
        const float* Ht = g_Hall + (size_t)t * NB * HD;

        // ---- GEMM1: pre-acts for [z|r], columns [cta*32, cta*32+32) of 4096
        {
            float acc[2][4] = {{0.f,0.f,0.f,0.f},{0.f,0.f,0.f,0.f}};
            gemm64<2>(sm, g_H_hi, g_H_lo, g_Wzr_hi, g_Wzr_lo, 2 * HD, cta * 32, acc);

            const bool is_r  = (cta >= 64);
            const int  nbase = (is_r ? (cta - 64) : cta) * 32;
            const int  wn    = (warp >> 2) * 16;
            const int  r0    = wm + (lane >> 2);
            #pragma unroll
            for (int ni = 0; ni < 2; ni++) {
                const int c = wn + ni * 8 + (lane & 3) * 2;
                #pragma unroll
                for (int half = 0; half < 2; half++) {
                    const int r = r0 + half * 8;
                    #pragma unroll
                    for (int j = 0; j < 2; j++) {
                        const int n = nbase + c + j;
                        float pre = acc[ni][half * 2 + j] +
                                    xg[(size_t)r * (3 * HD) + (is_r ? HD : 0) + n];
                        float v = sigmoidf_(pre);
                        if (!is_r) {
                            g_Z[r * HD + n] = v;
                        } else {
                            float h  = Ht[(size_t)r * HD + n];
                            float rh = v * h;
                            __nv_bfloat16 hi = __float2bfloat16(rh);
                            g_RH_hi[r * HD + n] = hi;
                            g_RH_lo[r * HD + n] =
                                __float2bfloat16(rh - __bfloat162float(hi));
                        }
                    }
                }
            }
        }
        grid_sync();

        // ---- GEMM2: h-candidate pre-acts, columns [cta*16, cta*16+16) of 2048
        {
            float acc[2][4] = {{0.f,0.f,0.f,0.f},{0.f,0.f,0.f,0.f}};
            gemm64<1>(sm, g_RH_hi, g_RH_lo, g_Whh_hi, g_Whh_lo, HD, cta * 16, acc);

            const int wn = (warp >> 2) * 8;
            const int r0 = wm + (lane >> 2);
            const int c  = wn + (lane & 3) * 2;
            #pragma unroll
            for (int half = 0; half < 2; half++) {
                const int r = r0 + half * 8;
                #pragma unroll
                for (int j = 0; j < 2; j++) {
                    const int n = cta * 16 + c + j;
                    float pre = acc[0][half * 2 + j] +
                                xg[(size_t)r * (3 * HD) + 2 * HD + n];
                    float ht = tanhf(pre);
                    float z  = g_Z[r * HD + n];
                    float h  = Ht[(size_t)r * HD + n];
                    float hn = z * h + (1.f - z) * ht;
                    g_Hall[((size_t)(t + 1) * NB + r) * HD + n] = hn;
                    __nv_bfloat16 hi = __float2bfloat16(hn);
                    g_H_hi[r * HD + n] = hi;
                    g_H_lo[r * HD + n] = __float2bfloat16(hn - __bfloat162float(hi));
                }
            }
        }
        grid_sync();
    }
}

// ================= setup / copy kernels =======================================
__global__ void prep_weights(const float* __restrict__ Whz,
                             const float* __restrict__ Whr,
                             const float* __restrict__ Whh) {
    size_t i = (size_t)blockIdx.x * blockDim.x + threadIdx.x;
    if (i >= (size_t)HD * HD) return;
    size_t k = i / HD, n = i % HD;
    float z = Whz[i];
    __nv_bfloat16 zh = __float2bfloat16(z);
    g_Wzr_hi[k * (2 * HD) + n] = zh;
    g_Wzr_lo[k * (2 * HD) + n] = __float2bfloat16(z - __bfloat162float(zh));
    float r = Whr[i];
    __nv_bfloat16 rh = __float2bfloat16(r);
    g_Wzr_hi[k * (2 * HD) + HD + n] = rh;
    g_Wzr_lo[k * (2 * HD) + HD + n] = __float2bfloat16(r - __bfloat162float(rh));
    float w = Whh[i];
    __nv_bfloat16 wh = __float2bfloat16(w);
    g_Whh_hi[i] = wh;
    g_Whh_lo[i] = __float2bfloat16(w - __bfloat162float(wh));
}

__global__ void prep_state(const float* __restrict__ state) {
    int i = blockIdx.x * blockDim.x + threadIdx.x;
    if (i >= NB * HD) return;
    float h = state[i];
    g_Hall[i] = h;
    __nv_bfloat16 hi = __float2bfloat16(h);
    g_H_hi[i] = hi;
    g_H_lo[i] = __float2bfloat16(h - __bfloat162float(hi));
}

__global__ void copy_hfinal(float* __restrict__ dst) {
    int i = blockIdx.x * blockDim.x + threadIdx.x;
    if (i >= NB * HD) return;
    dst[i] = g_Hall[(size_t)T_STEPS * NB * HD + i];
}

// ================= launch ======================================================
extern "C" void kernel_launch(void* const* d_in, const int* in_sizes, int n_in,
                              void* d_out, int out_size) {
    const float* X     = (const float*)d_in[0];
    const float* state = (const float*)d_in[1];
    const float* W_xz  = (const float*)d_in[2];
    const float* W_hz  = (const float*)d_in[3];
    const float* b_z   = (const float*)d_in[4];
    const float* W_xr  = (const float*)d_in[5];
    const float* W_hr  = (const float*)d_in[6];
    const float* b_r   = (const float*)d_in[7];
    const float* W_xh  = (const float*)d_in[8];
    const float* W_hh  = (const float*)d_in[9];
    const float* b_h   = (const float*)d_in[10];
    const float* W_hq  = (const float*)d_in[11];
    const float* b_hq  = (const float*)d_in[12];
    float* out = (float*)d_out;

    float* pXG;
    float* pHall;
    cudaGetSymbolAddress((void**)&pXG,   g_XG);
    cudaGetSymbolAddress((void**)&pHall, g_Hall);

    // Setup: weight split + H_0
    prep_weights<<<(int)(((size_t)HD * HD + 255) / 256), 256>>>(W_hz, W_hr, W_hh);
    prep_state<<<(NB * HD + 255) / 256, 256>>>(state);

    // Phase A: XG[:, g*HD:(g+1)*HD] = X @ W_xg + b_g (parallel over all t)
    {
        dim3 grid(HD / 128, TBM / 128, 1);
        gemm_split3<128, 128, 64, 32><<<grid, 256>>>(X, ID, W_xz, HD,
            pXG + 0 * HD, 3 * HD, TBM, HD, ID, b_z);
        gemm_split3<128, 128, 64, 32><<<grid, 256>>>(X, ID, W_xr, HD,
            pXG + 1 * HD, 3 * HD, TBM, HD, ID, b_r);
        gemm_split3<128, 128, 64, 32><<<grid, 256>>>(X, ID, W_xh, HD,
            pXG + 2 * HD, 3 * HD, TBM, HD, ID, b_h);
    }

    // Phase B: entire 512-step recurrence in ONE persistent kernel
    gru_scan<<<NCTA, 256>>>();

    // Phase C: Y[t*B+b, :] = H_{t+1}[b, :] @ W_hq + b_hq (one big GEMM)
    gemm_split3<128, 128, 64, 32><<<dim3(ID / 128, TBM / 128, 1), 256>>>(
        pHall + (size_t)NB * HD, HD, W_hq, ID, out, ID,
        TBM, ID, HD, b_hq);

    // H_final (second tuple output) appended after Y
    if (out_size >= (int)((size_t)TBM * ID + (size_t)NB * HD)) {
        copy_hfinal<<<(NB * HD + 255) / 256, 256>>>(out + (size_t)TBM * ID);
    }
}